// round 6
// baseline (speedup 1.0000x reference)
#include <cuda_runtime.h>
#include <cuda_bf16.h>
#include <math.h>

#define HW 65536
#define CMID 64

// ---- scratch (device globals; allocation is forbidden) ----
__device__ float g_y[4 * CMID * HW];      // after input conv1x1  (64 MiB)
__device__ float g_edge[4 * CMID * HW];   // raw edge map         (64 MiB)
__device__ float g_sums[4 * CMID];        // per-(b,c) raw-edge sums
__device__ unsigned int g_maxbits;        // global max (float bits, all >= 0)
__device__ __nv_bfloat16 g_winh[64 * 256], g_winl[64 * 256];   // pre-split w_in
__device__ __nv_bfloat16 g_wouth[4 * 64 * 64], g_woutl[4 * 64 * 64]; // folded w_out

// ---- stage buffer layout (bytes, within one buffer) ----
#define XPITCH 136                        // bf16 elems per X row (128 + 8 pad)
#define WPITCH 72                         // bf16 elems per W row (64 + 8 pad)
#define XH_OFF 0                          // 64 x 136 x 2 = 17408
#define XL_OFF 17408
#define WH_OFF 34816                      // 64 x 72 x 2 = 9216
#define WL_OFF 44032
#define BUFSZ  53248
#define SMEM_SZ (2 * BUFSZ)

// ============================ PTX helpers ==================================
__device__ __forceinline__ unsigned smem_u32(const void* p) {
    unsigned a;
    asm("{ .reg .u64 t; cvta.to.shared.u64 t, %1; cvt.u32.u64 %0, t; }" : "=r"(a) : "l"(p));
    return a;
}
__device__ __forceinline__ void ldsm4t(unsigned& r0, unsigned& r1, unsigned& r2,
                                       unsigned& r3, unsigned a) {
    asm volatile("ldmatrix.sync.aligned.m8n8.x4.trans.shared.b16 {%0,%1,%2,%3}, [%4];"
                 : "=r"(r0), "=r"(r1), "=r"(r2), "=r"(r3) : "r"(a));
}
__device__ __forceinline__ void ldsm4(unsigned& r0, unsigned& r1, unsigned& r2,
                                      unsigned& r3, unsigned a) {
    asm volatile("ldmatrix.sync.aligned.m8n8.x4.shared.b16 {%0,%1,%2,%3}, [%4];"
                 : "=r"(r0), "=r"(r1), "=r"(r2), "=r"(r3) : "r"(a));
}
__device__ __forceinline__ void mma16816(float* d, const unsigned* a,
                                         unsigned b0, unsigned b1) {
    asm volatile("mma.sync.aligned.m16n8k16.row.col.f32.bf16.bf16.f32 "
                 "{%0,%1,%2,%3},{%4,%5,%6,%7},{%8,%9},{%0,%1,%2,%3};"
                 : "+f"(d[0]), "+f"(d[1]), "+f"(d[2]), "+f"(d[3])
                 : "r"(a[0]), "r"(a[1]), "r"(a[2]), "r"(a[3]), "r"(b0), "r"(b1));
}
__device__ __forceinline__ unsigned pk(float a, float b) {
    __nv_bfloat162 t(__float2bfloat16(a), __float2bfloat16(b));
    return *(unsigned*)&t;
}
#define BAR_SYNC(id)   asm volatile("bar.sync %0, 192;"   :: "r"(id) : "memory")
#define BAR_ARRIVE(id) asm volatile("bar.arrive %0, 192;" :: "r"(id) : "memory")

// ===========================================================================
// Prep kernels: pre-split weights to bf16 hi/lo (run once per replay).
__global__ void k_prep_in(const float* __restrict__ w_in) {
    int tid = threadIdx.x;
    g_sums[tid] = 0.f;
    if (tid == 0) g_maxbits = 0u;
    for (int i = tid; i < 64 * 256; i += 256) {
        float v = w_in[i];
        float h = __bfloat162float(__float2bfloat16(v));
        g_winh[i] = __float2bfloat16(h);
        g_winl[i] = __float2bfloat16(v - h);
    }
}

__global__ void k_prep_out(const float* __restrict__ w_fc1, const float* __restrict__ b_fc1,
                           const float* __restrict__ w_fc2, const float* __restrict__ b_fc2,
                           const float* __restrict__ w_out) {
    __shared__ float pooled[4][64];
    __shared__ float hh[4][4];
    __shared__ float fm[4][64];
    int tid = threadIdx.x;
    int b = tid >> 6, c = tid & 63;
    float inv = 1.f / (__uint_as_float(g_maxbits) + 1e-8f);
    pooled[b][c] = g_sums[tid] * (1.f / 65536.f) * inv;
    __syncthreads();
    if (tid < 16) {
        int bb = tid >> 2, j = tid & 3;
        float s = b_fc1[j];
        for (int cc = 0; cc < 64; ++cc) s = fmaf(w_fc1[j * 64 + cc], pooled[bb][cc], s);
        hh[bb][j] = fmaxf(s, 0.f);
    }
    __syncthreads();
    {
        float sc = b_fc2[c];
#pragma unroll
        for (int j = 0; j < 4; ++j) sc = fmaf(w_fc2[c * 4 + j], hh[b][j], sc);
        fm[b][c] = inv / (1.f + expf(-sc));
    }
    __syncthreads();
    for (int i = tid; i < 4 * 64 * 64; i += 256) {
        int cc = i & 63, bb = i >> 12;
        int oo = (i >> 6) & 63;
        float v = w_out[oo * 64 + cc] * fm[bb][cc];
        float h = __bfloat162float(__float2bfloat16(v));
        g_wouth[i] = __float2bfloat16(h);
        g_woutl[i] = __float2bfloat16(v - h);
    }
}

// ===========================================================================
// conv1x1 via mma.sync bf16 3-term split, warp-specialized:
//   warps 0-3: consumers (each m32 x n64 of the 128pix x 64out tile)
//   warps 4-5: producers (LDG fp32 -> bf16 hi/lo split -> STS; W hi/lo copy)
// Double-buffered stages; named barriers 1,2 = full[0,1], 3,4 = empty[0,1].
template <int CHUNKS>
__global__ void __launch_bounds__(192) k_conv(
    const float* __restrict__ src, int cin,
    const __nv_bfloat16* __restrict__ wh_g, const __nv_bfloat16* __restrict__ wl_g,
    int wrow, int wbatch,
    const float* __restrict__ bias, float* __restrict__ dst) {
    extern __shared__ char sm[];
    unsigned smb = smem_u32(sm);
    int tid = threadIdx.x;
    int w   = tid >> 5, lane = tid & 31;

    int t    = blockIdx.x;
    int b    = t >> 9;           // 512 tiles per batch
    int pix0 = (t & 511) << 7;   // 128 pixels per tile

    if (w >= 4) {
        // ======================= PRODUCER =======================
        int pw = w - 4;                       // 0 or 1
        int ptid = pw * 32 + lane;            // 0..63
        const float* srcb = src + (size_t)b * cin * HW + pix0;
        const __nv_bfloat16* whb = wh_g + (size_t)b * wbatch;
        const __nv_bfloat16* wlb = wl_g + (size_t)b * wbatch;

        for (int s = 0; s < CHUNKS; ++s) {
            if (s >= 2) BAR_SYNC(3 + (s & 1));           // wait buffer free
            unsigned base = smb + (unsigned)((s & 1) * BUFSZ);
            char* smbuf = sm + (s & 1) * BUFSZ;

            // X: 32 rows per producer warp; each row = 512B contiguous LDG
            const float* xc = srcb + (size_t)(s * 64 + pw * 32) * HW + lane * 4;
#pragma unroll 4
            for (int r = 0; r < 32; ++r) {
                int c = pw * 32 + r;
                float4 v = *(const float4*)(xc + (size_t)r * HW);
                float h0 = __bfloat162float(__float2bfloat16(v.x));
                float h1 = __bfloat162float(__float2bfloat16(v.y));
                float h2 = __bfloat162float(__float2bfloat16(v.z));
                float h3 = __bfloat162float(__float2bfloat16(v.w));
                uint2 hv = make_uint2(pk(h0, h1), pk(h2, h3));
                uint2 lv = make_uint2(pk(v.x - h0, v.y - h1), pk(v.z - h2, v.w - h3));
                unsigned off = (unsigned)((c * XPITCH + lane * 4) * 2);
                *(uint2*)(smbuf + XH_OFF + off) = hv;
                *(uint2*)(smbuf + XL_OFF + off) = lv;
            }
            // W: 512 uint4 each for hi and lo; 64 producer threads x 8
#pragma unroll
            for (int k = 0; k < 8; ++k) {
                int idx = ptid + k * 64;
                int o = idx >> 3, c8 = (idx & 7) * 8;
                int gsrc = o * wrow + s * 64 + c8;
                unsigned doff = (unsigned)((o * WPITCH + c8) * 2);
                *(uint4*)(smbuf + WH_OFF + doff) = *(const uint4*)(whb + gsrc);
                *(uint4*)(smbuf + WL_OFF + doff) = *(const uint4*)(wlb + gsrc);
            }
            (void)base;
            BAR_SYNC(1 + (s & 1));                       // publish (sync drains STS)
        }
    } else {
        // ======================= CONSUMER =======================
        float acc[2][8][4];
#pragma unroll
        for (int mt = 0; mt < 2; ++mt)
#pragma unroll
            for (int nt = 0; nt < 8; ++nt)
#pragma unroll
                for (int i = 0; i < 4; ++i) acc[mt][nt][i] = 0.f;

        int arow  = (lane & 7) + ((lane >> 4) << 3);
        int acol0 = (w << 5) + (((lane >> 3) & 1) << 3);
        int brow2 = ((lane >> 4) << 3) + (lane & 7);
        int bcol  = ((lane >> 3) & 1) << 3;

        for (int s = 0; s < CHUNKS; ++s) {
            BAR_SYNC(1 + (s & 1));                       // wait buffer full
            unsigned base = smb + (unsigned)((s & 1) * BUFSZ);
#pragma unroll
            for (int ks = 0; ks < 4; ++ks) {
                unsigned ah[2][4], al[2][4];
#pragma unroll
                for (int mt = 0; mt < 2; ++mt) {
                    unsigned aoff = (unsigned)(((ks * 16 + arow) * XPITCH + acol0 + mt * 16) * 2);
                    ldsm4t(ah[mt][0], ah[mt][1], ah[mt][2], ah[mt][3], base + XH_OFF + aoff);
                    ldsm4t(al[mt][0], al[mt][1], al[mt][2], al[mt][3], base + XL_OFF + aoff);
                }
#pragma unroll
                for (int ntp = 0; ntp < 4; ++ntp) {
                    unsigned bh[4], bl[4];
                    unsigned boff = (unsigned)(((ntp * 16 + brow2) * WPITCH + ks * 16 + bcol) * 2);
                    ldsm4(bh[0], bh[1], bh[2], bh[3], base + WH_OFF + boff);
                    ldsm4(bl[0], bl[1], bl[2], bl[3], base + WL_OFF + boff);
#pragma unroll
                    for (int mt = 0; mt < 2; ++mt) {
                        mma16816(acc[mt][ntp * 2],     ah[mt], bh[0], bh[1]);
                        mma16816(acc[mt][ntp * 2],     al[mt], bh[0], bh[1]);
                        mma16816(acc[mt][ntp * 2],     ah[mt], bl[0], bl[1]);
                        mma16816(acc[mt][ntp * 2 + 1], ah[mt], bh[2], bh[3]);
                        mma16816(acc[mt][ntp * 2 + 1], al[mt], bh[2], bh[3]);
                        mma16816(acc[mt][ntp * 2 + 1], ah[mt], bl[2], bl[3]);
                    }
                }
            }
            if (s + 2 < CHUNKS) BAR_ARRIVE(3 + (s & 1)); // release buffer
        }

        // ---- epilogue: C[m=pix][n=out] fragments -> dst[o][pix] + bias
        int g  = lane >> 2;
        int t2 = (lane & 3) * 2;
#pragma unroll
        for (int mt = 0; mt < 2; ++mt) {
            float* dp = dst + (size_t)b * CMID * HW + pix0 + w * 32 + mt * 16;
#pragma unroll
            for (int nt = 0; nt < 8; ++nt) {
                int o0 = nt * 8 + t2;
                float b0 = __ldg(bias + o0), b1 = __ldg(bias + o0 + 1);
                dp[(size_t)o0 * HW + g]           = acc[mt][nt][0] + b0;
                dp[(size_t)(o0 + 1) * HW + g]     = acc[mt][nt][1] + b1;
                dp[(size_t)o0 * HW + g + 8]       = acc[mt][nt][2] + b0;
                dp[(size_t)(o0 + 1) * HW + g + 8] = acc[mt][nt][3] + b1;
            }
        }
    }
}

// ---------------------------------------------------------------------------
// Fused depthwise stage (identical to the 526us run)
__global__ void __launch_bounds__(256) k_edge() {
    __shared__ float ys[38][40];
    __shared__ float ts[34][40];
    __shared__ float ss[34][36];
    __shared__ float rs[8], rm[8];

    int tid   = threadIdx.x;
    int plane = blockIdx.y;
    int tile  = blockIdx.x;
    int ty0 = (tile >> 3) * 32;
    int tx0 = (tile & 7) * 32;
    const float* yp = g_y + (size_t)plane * HW;

    for (int i = tid; i < 38 * 38; i += 256) {
        int r = i / 38, c = i - r * 38;
        int gy = ty0 - 3 + r, gx = tx0 - 3 + c;
        float v = 0.f;
        if ((unsigned)gy < 256u && (unsigned)gx < 256u) v = yp[gy * 256 + gx];
        ys[r][c] = v;
    }
    __syncthreads();

    float g1 = expf(-0.125f), g2 = expf(-0.5f);
    float sg = 1.f + 2.f * g1 + 2.f * g2;
    float invS = 1.f / (sg * sg);

    for (int i = tid; i < 34 * 38; i += 256) {
        int r = i / 38, c = i - r * 38;
        ts[r][c] = g2 * (ys[r][c] + ys[r + 4][c]) +
                   g1 * (ys[r + 1][c] + ys[r + 3][c]) + ys[r + 2][c];
    }
    __syncthreads();

    for (int i = tid; i < 34 * 34; i += 256) {
        int r = i / 34, c = i - r * 34;
        float v = g2 * (ts[r][c] + ts[r][c + 4]) +
                  g1 * (ts[r][c + 1] + ts[r][c + 3]) + ts[r][c + 2];
        v *= invS;
        int gy = ty0 - 1 + r, gx = tx0 - 1 + c;
        if ((unsigned)gy >= 256u || (unsigned)gx >= 256u) v = 0.f;
        ss[r][c] = v;
    }
    __syncthreads();

    int col = tid & 31;
    int rb  = tid >> 5;
    float lsum = 0.f, lmax = 0.f;
    float* ep = g_edge + (size_t)plane * HW;
#pragma unroll
    for (int q = 0; q < 4; ++q) {
        int r = rb + q * 8;
        float a  = ss[r][col],     bb = ss[r][col + 1],     cv = ss[r][col + 2];
        float d  = ss[r + 1][col], e  = ss[r + 1][col + 1], f  = ss[r + 1][col + 2];
        float g  = ss[r + 2][col], h  = ss[r + 2][col + 1], ii = ss[r + 2][col + 2];
        float g0  = 3.f * (a - cv) + 10.f * (d - f) + 3.f * (g - ii);
        float g90 = 3.f * (a - g)  + 10.f * (bb - h) + 3.f * (cv - ii);
        float lap = 4.f * e - bb - d - f - h;
        float edge = fmaxf(fabsf(g0), fabsf(g90)) + 0.1f * fabsf(lap);
        ep[(ty0 + r) * 256 + tx0 + col] = edge;
        lsum += edge;
        lmax = fmaxf(lmax, edge);
    }

#pragma unroll
    for (int off = 16; off; off >>= 1) {
        lsum += __shfl_down_sync(0xffffffffu, lsum, off);
        lmax = fmaxf(lmax, __shfl_down_sync(0xffffffffu, lmax, off));
    }
    int wid = tid >> 5, lane = tid & 31;
    if (lane == 0) { rs[wid] = lsum; rm[wid] = lmax; }
    __syncthreads();
    if (tid == 0) {
        float s = 0.f, m = 0.f;
#pragma unroll
        for (int w2 = 0; w2 < 8; ++w2) { s += rs[w2]; m = fmaxf(m, rm[w2]); }
        atomicAdd(&g_sums[plane], s);
        atomicMax(&g_maxbits, __float_as_uint(m));
    }
}

// ---------------------------------------------------------------------------
extern "C" void kernel_launch(void* const* d_in, const int* in_sizes, int n_in,
                              void* d_out, int out_size) {
    const float* x     = (const float*)d_in[0];
    const float* w_in  = (const float*)d_in[1];
    const float* b_in  = (const float*)d_in[2];
    const float* w_fc1 = (const float*)d_in[3];
    const float* b_fc1 = (const float*)d_in[4];
    const float* w_fc2 = (const float*)d_in[5];
    const float* b_fc2 = (const float*)d_in[6];
    const float* w_out = (const float*)d_in[7];
    const float* b_out = (const float*)d_in[8];
    float* out = (float*)d_out;

    cudaFuncSetAttribute(k_conv<4>, cudaFuncAttributeMaxDynamicSharedMemorySize, SMEM_SZ);
    cudaFuncSetAttribute(k_conv<1>, cudaFuncAttributeMaxDynamicSharedMemorySize, SMEM_SZ);

    float* gy = nullptr;
    float* gedge = nullptr;
    __nv_bfloat16 *winh, *winl, *wouth, *woutl;
    cudaGetSymbolAddress((void**)&gy, g_y);
    cudaGetSymbolAddress((void**)&gedge, g_edge);
    cudaGetSymbolAddress((void**)&winh, g_winh);
    cudaGetSymbolAddress((void**)&winl, g_winl);
    cudaGetSymbolAddress((void**)&wouth, g_wouth);
    cudaGetSymbolAddress((void**)&woutl, g_woutl);

    k_prep_in<<<1, 256>>>(w_in);
    k_conv<4><<<2048, 192, SMEM_SZ>>>(x, 256, winh, winl, 256, 0, b_in, gy);
    k_edge<<<dim3(64, 256), 256>>>();
    k_prep_out<<<1, 256>>>(w_fc1, b_fc1, w_fc2, b_fc2, w_out);
    k_conv<1><<<2048, 192, SMEM_SZ>>>(gedge, 64, wouth, woutl, 64, 4096, b_out, out);
}

// round 7
// speedup vs baseline: 1.5640x; 1.5640x over previous
#include <cuda_runtime.h>
#include <cuda_bf16.h>
#include <math.h>

#define HW 65536
#define CMID 64

// ---- scratch (device globals; allocation is forbidden) ----
__device__ float g_y[4 * CMID * HW];      // after input conv1x1  (64 MiB)
__device__ float g_edge[4 * CMID * HW];   // raw edge map         (64 MiB)
__device__ float g_sums[4 * CMID];        // per-(b,c) raw-edge sums
__device__ unsigned int g_maxbits;        // global max (float bits, all >= 0)

// ---- dynamic smem layout (bytes) ----
#define XSP 132                           // fp32 staging pitch (floats)
#define XS0_OFF 0                         // 32 x 132 x 4 = 16896
#define XS1_OFF 16896
#define XPITCH 136                        // bf16 X pitch
#define XH_OFF 33792                      // 32 x 136 x 2 = 8704
#define XL_OFF 42496
#define WPITCH 40                         // bf16 W pitch (32 + 8 pad)
#define WH_OFF 51200                      // 64 x 40 x 2 = 5120
#define WL_OFF 56320
#define FM_OFF 61440
#define PL_OFF 61696
#define HH_OFF 61952
#define SMEM_SZ 62208

// ============================ PTX helpers ==================================
__device__ __forceinline__ unsigned smem_u32(const void* p) {
    unsigned a;
    asm("{ .reg .u64 t; cvta.to.shared.u64 t, %1; cvt.u32.u64 %0, t; }" : "=r"(a) : "l"(p));
    return a;
}
__device__ __forceinline__ void cpa16(unsigned d, const void* s) {
    asm volatile("cp.async.cg.shared.global [%0], [%1], 16;" :: "r"(d), "l"(s));
}
#define CPCOMMIT() asm volatile("cp.async.commit_group;" ::: "memory")
template <int N> __device__ __forceinline__ void cpwait() {
    asm volatile("cp.async.wait_group %0;" :: "n"(N) : "memory");
}
__device__ __forceinline__ void ldsm4t(unsigned& r0, unsigned& r1, unsigned& r2,
                                       unsigned& r3, unsigned a) {
    asm volatile("ldmatrix.sync.aligned.m8n8.x4.trans.shared.b16 {%0,%1,%2,%3}, [%4];"
                 : "=r"(r0), "=r"(r1), "=r"(r2), "=r"(r3) : "r"(a));
}
__device__ __forceinline__ void ldsm4(unsigned& r0, unsigned& r1, unsigned& r2,
                                      unsigned& r3, unsigned a) {
    asm volatile("ldmatrix.sync.aligned.m8n8.x4.shared.b16 {%0,%1,%2,%3}, [%4];"
                 : "=r"(r0), "=r"(r1), "=r"(r2), "=r"(r3) : "r"(a));
}
__device__ __forceinline__ void mma16816(float* d, const unsigned* a,
                                         unsigned b0, unsigned b1) {
    asm volatile("mma.sync.aligned.m16n8k16.row.col.f32.bf16.bf16.f32 "
                 "{%0,%1,%2,%3},{%4,%5,%6,%7},{%8,%9},{%0,%1,%2,%3};"
                 : "+f"(d[0]), "+f"(d[1]), "+f"(d[2]), "+f"(d[3])
                 : "r"(a[0]), "r"(a[1]), "r"(a[2]), "r"(a[3]), "r"(b0), "r"(b1));
}
__device__ __forceinline__ unsigned pk(float a, float b) {
    __nv_bfloat162 t(__float2bfloat16(a), __float2bfloat16(b));
    return *(unsigned*)&t;
}

// ===========================================================================
// conv1x1 via mma.sync bf16 3-term split + cp.async pipelined staging.
// 128 threads / 4 warps; each warp m32 x n64. Chunks of 32 channels.
// Pipeline: cp.async X(s+2) overlaps convert(s)+MMA(s); W LDG (L2-hot)
// hidden behind the convert LDS chain.
template <int CH, int FOLD>
__global__ void __launch_bounds__(128, 3) k_conv(
    const float* __restrict__ src, int cin,
    const float* __restrict__ wsrc, int wrow,
    const float* __restrict__ bias, float* __restrict__ dst,
    const float* __restrict__ w_fc1, const float* __restrict__ b_fc1,
    const float* __restrict__ w_fc2, const float* __restrict__ b_fc2) {
    extern __shared__ char sm[];
    unsigned smb = smem_u32(sm);
    int tid = threadIdx.x;
    int w   = tid >> 5, lane = tid & 31;

    int t    = blockIdx.x;
    int b    = t >> 9;           // 512 tiles per batch
    int pix0 = (t & 511) << 7;   // 128 pixels per tile

    if (!FOLD && blockIdx.x == 0) {   // init for this replay's edge stage
        g_sums[tid] = 0.f;
        g_sums[tid + 128] = 0.f;
        if (tid == 0) g_maxbits = 0u;
    }

    if (FOLD) {   // SE head: per-channel fmul = sigmoid(fc2(relu(fc1(pooled))))*inv
        float* pooled = (float*)(sm + PL_OFF);
        float* hh     = (float*)(sm + HH_OFF);
        float* fm     = (float*)(sm + FM_OFF);
        float inv = 1.f / (__uint_as_float(g_maxbits) + 1e-8f);
        if (tid < 64) pooled[tid] = g_sums[b * 64 + tid] * (1.f / 65536.f) * inv;
        __syncthreads();
        if (tid < 4) {
            float s = b_fc1[tid];
            for (int cc = 0; cc < 64; ++cc) s = fmaf(w_fc1[tid * 64 + cc], pooled[cc], s);
            hh[tid] = fmaxf(s, 0.f);
        }
        __syncthreads();
        if (tid < 64) {
            float sc = b_fc2[tid];
#pragma unroll
            for (int j = 0; j < 4; ++j) sc = fmaf(w_fc2[tid * 4 + j], hh[j], sc);
            fm[tid] = inv / (1.f + expf(-sc));
        }
        __syncthreads();
    }

    const float* srcb = src + (size_t)b * cin * HW + pix0;

    // ---- cp.async issue of one 32-channel X chunk into staging buffer
    auto issue_x = [&](int cs, int buf) {
        const float* base = srcb + (size_t)(cs * 32) * HW;
        unsigned db = smb + (buf ? XS1_OFF : XS0_OFF);
#pragma unroll
        for (int k = 0; k < 8; ++k) {
            int seg = tid + k * 128;               // 0..1023
            int row = seg >> 5, off = (seg & 31) * 4;
            cpa16(db + (unsigned)(row * XSP + off) * 4, base + (size_t)row * HW + off);
        }
    };

    issue_x(0, 0); CPCOMMIT();
    if (CH > 1) { issue_x(1, 1); CPCOMMIT(); }

    float acc[2][8][4];
#pragma unroll
    for (int mt = 0; mt < 2; ++mt)
#pragma unroll
        for (int nt = 0; nt < 8; ++nt)
#pragma unroll
            for (int i = 0; i < 4; ++i) acc[mt][nt][i] = 0.f;

    // ldmatrix address components
    int arow  = (lane & 7) + ((lane >> 4) << 3);
    int acol0 = (w << 5) + (((lane >> 3) & 1) << 3);
    int brow2 = ((lane >> 4) << 3) + (lane & 7);
    int bcol  = ((lane >> 3) & 1) << 3;

    for (int s = 0; s < CH; ++s) {
        if (s + 1 < CH) cpwait<1>(); else cpwait<0>();
        __syncthreads();

        // ---- W LDG first (L2-hot; latency hidden behind X convert below)
        int wo = tid >> 1, wc = (tid & 1) * 16;
        const float* wp = wsrc + wo * wrow + s * 32 + wc;
        float4 wa = *(const float4*)wp;
        float4 wb4 = *(const float4*)(wp + 4);
        float4 wcv = *(const float4*)(wp + 8);
        float4 wd = *(const float4*)(wp + 12);

        // ---- X convert: XS[s&1] fp32 [c][pix] -> XH/XL bf16 (lane=row, warp=colblock)
        {
            const char* xs = sm + ((s & 1) ? XS1_OFF : XS0_OFF);
            int cw = w * 32;
            unsigned hibuf[16], lobuf[16];
#pragma unroll
            for (int i = 0; i < 8; ++i) {
                float4 v = *(const float4*)(xs + (lane * XSP + cw + i * 4) * 4);
                float h0 = __bfloat162float(__float2bfloat16(v.x));
                float h1 = __bfloat162float(__float2bfloat16(v.y));
                float h2 = __bfloat162float(__float2bfloat16(v.z));
                float h3 = __bfloat162float(__float2bfloat16(v.w));
                hibuf[i * 2]     = pk(h0, h1);
                hibuf[i * 2 + 1] = pk(h2, h3);
                lobuf[i * 2]     = pk(v.x - h0, v.y - h1);
                lobuf[i * 2 + 1] = pk(v.z - h2, v.w - h3);
            }
            unsigned xoff = (unsigned)((lane * XPITCH + cw) * 2);
#pragma unroll
            for (int j = 0; j < 4; ++j) {
                *(uint4*)(sm + XH_OFF + xoff + j * 16) =
                    make_uint4(hibuf[j * 4], hibuf[j * 4 + 1], hibuf[j * 4 + 2], hibuf[j * 4 + 3]);
                *(uint4*)(sm + XL_OFF + xoff + j * 16) =
                    make_uint4(lobuf[j * 4], lobuf[j * 4 + 1], lobuf[j * 4 + 2], lobuf[j * 4 + 3]);
            }
        }

        // ---- W split + STS (FOLD: scale by fm first)
        {
            float wv[16] = {wa.x, wa.y, wa.z, wa.w, wb4.x, wb4.y, wb4.z, wb4.w,
                            wcv.x, wcv.y, wcv.z, wcv.w, wd.x, wd.y, wd.z, wd.w};
            if (FOLD) {
                const float* fm = (const float*)(sm + FM_OFF);
#pragma unroll
                for (int i = 0; i < 16; ++i) wv[i] *= fm[s * 32 + wc + i];
            }
            unsigned hb[4], lb[4];
#pragma unroll
            for (int i = 0; i < 8; ++i) {
                float h0 = __bfloat162float(__float2bfloat16(wv[i * 2]));
                float h1 = __bfloat162float(__float2bfloat16(wv[i * 2 + 1]));
                hb[i / 2] = (i & 1) ? (hb[i / 2] | ((unsigned)pk(h0, h1) << 0), hb[i / 2]) : hb[i / 2];
                (void)h0; (void)h1;
            }
            // simpler: build 4+4 packed words directly
#pragma unroll
            for (int i = 0; i < 4; ++i) {
                float h0 = __bfloat162float(__float2bfloat16(wv[i * 4]));
                float h1 = __bfloat162float(__float2bfloat16(wv[i * 4 + 1]));
                float h2 = __bfloat162float(__float2bfloat16(wv[i * 4 + 2]));
                float h3 = __bfloat162float(__float2bfloat16(wv[i * 4 + 3]));
                hb[i] = 0; lb[i] = 0;
                ((unsigned short*)&hb[i])[0] = ((unsigned short*)&(unsigned&)hb[i])[0];
                // pack two bf16x2 per 2 elems:
                unsigned p0 = pk(h0, h1), p1 = pk(h2, h3);
                unsigned q0 = pk(wv[i * 4] - h0, wv[i * 4 + 1] - h1);
                unsigned q1 = pk(wv[i * 4 + 2] - h2, wv[i * 4 + 3] - h3);
                // store 8B at a time
                unsigned woff = (unsigned)((wo * WPITCH + wc + i * 4) * 2);
                *(uint2*)(sm + WH_OFF + woff) = make_uint2(p0, p1);
                *(uint2*)(sm + WL_OFF + woff) = make_uint2(q0, q1);
            }
        }
        __syncthreads();

        if (s + 2 < CH) { issue_x(s + 2, s & 1); CPCOMMIT(); }

        // ---- MMA: 2 k-steps of 16
#pragma unroll
        for (int ks = 0; ks < 2; ++ks) {
            unsigned ah[2][4], al[2][4];
#pragma unroll
            for (int mt = 0; mt < 2; ++mt) {
                unsigned aoff = (unsigned)(((ks * 16 + arow) * XPITCH + acol0 + mt * 16) * 2);
                ldsm4t(ah[mt][0], ah[mt][1], ah[mt][2], ah[mt][3], smb + XH_OFF + aoff);
                ldsm4t(al[mt][0], al[mt][1], al[mt][2], al[mt][3], smb + XL_OFF + aoff);
            }
#pragma unroll
            for (int ntp = 0; ntp < 4; ++ntp) {
                unsigned bh[4], bl[4];
                unsigned boff = (unsigned)(((ntp * 16 + brow2) * WPITCH + ks * 16 + bcol) * 2);
                ldsm4(bh[0], bh[1], bh[2], bh[3], smb + WH_OFF + boff);
                ldsm4(bl[0], bl[1], bl[2], bl[3], smb + WL_OFF + boff);
#pragma unroll
                for (int mt = 0; mt < 2; ++mt) {
                    mma16816(acc[mt][ntp * 2],     ah[mt], bh[0], bh[1]);
                    mma16816(acc[mt][ntp * 2],     al[mt], bh[0], bh[1]);
                    mma16816(acc[mt][ntp * 2],     ah[mt], bl[0], bl[1]);
                    mma16816(acc[mt][ntp * 2 + 1], ah[mt], bh[2], bh[3]);
                    mma16816(acc[mt][ntp * 2 + 1], al[mt], bh[2], bh[3]);
                    mma16816(acc[mt][ntp * 2 + 1], ah[mt], bl[2], bl[3]);
                }
            }
        }
        // top-of-loop __syncthreads() orders next convert after these ldsm reads
    }

    // ---- epilogue: C[m=pix][n=out] fragments -> dst[o][pix] + bias
    int g  = lane >> 2;
    int t2 = (lane & 3) * 2;
#pragma unroll
    for (int mt = 0; mt < 2; ++mt) {
        float* dp = dst + (size_t)b * CMID * HW + pix0 + w * 32 + mt * 16;
#pragma unroll
        for (int nt = 0; nt < 8; ++nt) {
            int o0 = nt * 8 + t2;
            float b0 = __ldg(bias + o0), b1 = __ldg(bias + o0 + 1);
            dp[(size_t)o0 * HW + g]           = acc[mt][nt][0] + b0;
            dp[(size_t)(o0 + 1) * HW + g]     = acc[mt][nt][1] + b1;
            dp[(size_t)o0 * HW + g + 8]       = acc[mt][nt][2] + b0;
            dp[(size_t)(o0 + 1) * HW + g + 8] = acc[mt][nt][3] + b1;
        }
    }
}

// ---------------------------------------------------------------------------
// Fused depthwise stage (identical to the 526us run)
__global__ void __launch_bounds__(256) k_edge() {
    __shared__ float ys[38][40];
    __shared__ float ts[34][40];
    __shared__ float ss[34][36];
    __shared__ float rs[8], rm[8];

    int tid   = threadIdx.x;
    int plane = blockIdx.y;
    int tile  = blockIdx.x;
    int ty0 = (tile >> 3) * 32;
    int tx0 = (tile & 7) * 32;
    const float* yp = g_y + (size_t)plane * HW;

    for (int i = tid; i < 38 * 38; i += 256) {
        int r = i / 38, c = i - r * 38;
        int gy = ty0 - 3 + r, gx = tx0 - 3 + c;
        float v = 0.f;
        if ((unsigned)gy < 256u && (unsigned)gx < 256u) v = yp[gy * 256 + gx];
        ys[r][c] = v;
    }
    __syncthreads();

    float g1 = expf(-0.125f), g2 = expf(-0.5f);
    float sg = 1.f + 2.f * g1 + 2.f * g2;
    float invS = 1.f / (sg * sg);

    for (int i = tid; i < 34 * 38; i += 256) {
        int r = i / 38, c = i - r * 38;
        ts[r][c] = g2 * (ys[r][c] + ys[r + 4][c]) +
                   g1 * (ys[r + 1][c] + ys[r + 3][c]) + ys[r + 2][c];
    }
    __syncthreads();

    for (int i = tid; i < 34 * 34; i += 256) {
        int r = i / 34, c = i - r * 34;
        float v = g2 * (ts[r][c] + ts[r][c + 4]) +
                  g1 * (ts[r][c + 1] + ts[r][c + 3]) + ts[r][c + 2];
        v *= invS;
        int gy = ty0 - 1 + r, gx = tx0 - 1 + c;
        if ((unsigned)gy >= 256u || (unsigned)gx >= 256u) v = 0.f;
        ss[r][c] = v;
    }
    __syncthreads();

    int col = tid & 31;
    int rb  = tid >> 5;
    float lsum = 0.f, lmax = 0.f;
    float* ep = g_edge + (size_t)plane * HW;
#pragma unroll
    for (int q = 0; q < 4; ++q) {
        int r = rb + q * 8;
        float a  = ss[r][col],     bb = ss[r][col + 1],     cv = ss[r][col + 2];
        float d  = ss[r + 1][col], e  = ss[r + 1][col + 1], f  = ss[r + 1][col + 2];
        float g  = ss[r + 2][col], h  = ss[r + 2][col + 1], ii = ss[r + 2][col + 2];
        float g0  = 3.f * (a - cv) + 10.f * (d - f) + 3.f * (g - ii);
        float g90 = 3.f * (a - g)  + 10.f * (bb - h) + 3.f * (cv - ii);
        float lap = 4.f * e - bb - d - f - h;
        float edge = fmaxf(fabsf(g0), fabsf(g90)) + 0.1f * fabsf(lap);
        ep[(ty0 + r) * 256 + tx0 + col] = edge;
        lsum += edge;
        lmax = fmaxf(lmax, edge);
    }

#pragma unroll
    for (int off = 16; off; off >>= 1) {
        lsum += __shfl_down_sync(0xffffffffu, lsum, off);
        lmax = fmaxf(lmax, __shfl_down_sync(0xffffffffu, lmax, off));
    }
    int wid = tid >> 5, lane = tid & 31;
    if (lane == 0) { rs[wid] = lsum; rm[wid] = lmax; }
    __syncthreads();
    if (tid == 0) {
        float s = 0.f, m = 0.f;
#pragma unroll
        for (int w2 = 0; w2 < 8; ++w2) { s += rs[w2]; m = fmaxf(m, rm[w2]); }
        atomicAdd(&g_sums[plane], s);
        atomicMax(&g_maxbits, __float_as_uint(m));
    }
}

// ---------------------------------------------------------------------------
extern "C" void kernel_launch(void* const* d_in, const int* in_sizes, int n_in,
                              void* d_out, int out_size) {
    const float* x     = (const float*)d_in[0];
    const float* w_in  = (const float*)d_in[1];
    const float* b_in  = (const float*)d_in[2];
    const float* w_fc1 = (const float*)d_in[3];
    const float* b_fc1 = (const float*)d_in[4];
    const float* w_fc2 = (const float*)d_in[5];
    const float* b_fc2 = (const float*)d_in[6];
    const float* w_out = (const float*)d_in[7];
    const float* b_out = (const float*)d_in[8];
    float* out = (float*)d_out;

    cudaFuncSetAttribute(k_conv<8, 0>, cudaFuncAttributeMaxDynamicSharedMemorySize, SMEM_SZ);
    cudaFuncSetAttribute(k_conv<2, 1>, cudaFuncAttributeMaxDynamicSharedMemorySize, SMEM_SZ);

    float* gy = nullptr;
    float* gedge = nullptr;
    cudaGetSymbolAddress((void**)&gy, g_y);
    cudaGetSymbolAddress((void**)&gedge, g_edge);

    // conv_in: 8 chunks of 32 channels; block 0 zeroes g_sums/g_maxbits
    k_conv<8, 0><<<2048, 128, SMEM_SZ>>>(x, 256, w_in, 256, b_in, gy,
                                         nullptr, nullptr, nullptr, nullptr);
    k_edge<<<dim3(64, 256), 256>>>();
    // conv_out: 2 chunks; SE head fused + folded into W staging
    k_conv<2, 1><<<2048, 128, SMEM_SZ>>>(gedge, 64, w_out, 64, b_out, out,
                                         w_fc1, b_fc1, w_fc2, b_fc2);
}

// round 8
// speedup vs baseline: 1.6260x; 1.0397x over previous
#include <cuda_runtime.h>
#include <cuda_bf16.h>
#include <math.h>

#define HW 65536
#define CMID 64

// ---- scratch (device globals; allocation is forbidden) ----
__device__ float g_y[4 * CMID * HW];      // after input conv1x1  (64 MiB)
__device__ float g_edge[4 * CMID * HW];   // raw edge map         (64 MiB)
__device__ float g_sums[4 * CMID];        // per-(b,c) raw-edge sums
__device__ unsigned int g_maxbits;        // global max (float bits, all >= 0)

// ---- dynamic smem layout (bytes) ----
#define XSP 132                           // fp32 staging pitch (floats)
#define XS0_OFF 0                         // 32 x 132 x 4 = 16896
#define XS1_OFF 16896
#define XPITCH 136                        // bf16 X pitch
#define XH_OFF 33792                      // 32 x 136 x 2 = 8704
#define XL_OFF 42496
#define WPITCH 40                         // bf16 W pitch (32 + 8 pad)
#define WH_OFF 51200                      // 64 x 40 x 2 = 5120
#define WL_OFF 56320
#define FM_OFF 61440
#define PL_OFF 61696
#define HH_OFF 61952
#define SMEM_SZ 62208

// ============================ PTX helpers ==================================
__device__ __forceinline__ unsigned smem_u32(const void* p) {
    unsigned a;
    asm("{ .reg .u64 t; cvta.to.shared.u64 t, %1; cvt.u32.u64 %0, t; }" : "=r"(a) : "l"(p));
    return a;
}
__device__ __forceinline__ void cpa16(unsigned d, const void* s) {
    asm volatile("cp.async.cg.shared.global [%0], [%1], 16;" :: "r"(d), "l"(s));
}
#define CPCOMMIT() asm volatile("cp.async.commit_group;" ::: "memory")
template <int N> __device__ __forceinline__ void cpwait() {
    asm volatile("cp.async.wait_group %0;" :: "n"(N) : "memory");
}
__device__ __forceinline__ void ldsm4t(unsigned& r0, unsigned& r1, unsigned& r2,
                                       unsigned& r3, unsigned a) {
    asm volatile("ldmatrix.sync.aligned.m8n8.x4.trans.shared.b16 {%0,%1,%2,%3}, [%4];"
                 : "=r"(r0), "=r"(r1), "=r"(r2), "=r"(r3) : "r"(a));
}
__device__ __forceinline__ void ldsm4(unsigned& r0, unsigned& r1, unsigned& r2,
                                      unsigned& r3, unsigned a) {
    asm volatile("ldmatrix.sync.aligned.m8n8.x4.shared.b16 {%0,%1,%2,%3}, [%4];"
                 : "=r"(r0), "=r"(r1), "=r"(r2), "=r"(r3) : "r"(a));
}
__device__ __forceinline__ void mma16816(float* d, const unsigned* a,
                                         unsigned b0, unsigned b1) {
    asm volatile("mma.sync.aligned.m16n8k16.row.col.f32.bf16.bf16.f32 "
                 "{%0,%1,%2,%3},{%4,%5,%6,%7},{%8,%9},{%0,%1,%2,%3};"
                 : "+f"(d[0]), "+f"(d[1]), "+f"(d[2]), "+f"(d[3])
                 : "r"(a[0]), "r"(a[1]), "r"(a[2]), "r"(a[3]), "r"(b0), "r"(b1));
}
__device__ __forceinline__ unsigned pk(float a, float b) {
    __nv_bfloat162 t(__float2bfloat16(a), __float2bfloat16(b));
    return *(unsigned*)&t;
}

// ===========================================================================
// conv1x1 via mma.sync bf16 3-term split + cp.async pipelined staging.
// (identical to the 250.8us run, minus dead code in the W split)
template <int CH, int FOLD>
__global__ void __launch_bounds__(128, 3) k_conv(
    const float* __restrict__ src, int cin,
    const float* __restrict__ wsrc, int wrow,
    const float* __restrict__ bias, float* __restrict__ dst,
    const float* __restrict__ w_fc1, const float* __restrict__ b_fc1,
    const float* __restrict__ w_fc2, const float* __restrict__ b_fc2) {
    extern __shared__ char sm[];
    unsigned smb = smem_u32(sm);
    int tid = threadIdx.x;
    int w   = tid >> 5, lane = tid & 31;

    int t    = blockIdx.x;
    int b    = t >> 9;           // 512 tiles per batch
    int pix0 = (t & 511) << 7;   // 128 pixels per tile

    if (!FOLD && blockIdx.x == 0) {   // init for this replay's edge stage
        g_sums[tid] = 0.f;
        g_sums[tid + 128] = 0.f;
        if (tid == 0) g_maxbits = 0u;
    }

    if (FOLD) {   // SE head: per-channel fmul = sigmoid(fc2(relu(fc1(pooled))))*inv
        float* pooled = (float*)(sm + PL_OFF);
        float* hh     = (float*)(sm + HH_OFF);
        float* fm     = (float*)(sm + FM_OFF);
        float inv = 1.f / (__uint_as_float(g_maxbits) + 1e-8f);
        if (tid < 64) pooled[tid] = g_sums[b * 64 + tid] * (1.f / 65536.f) * inv;
        __syncthreads();
        if (tid < 4) {
            float s = b_fc1[tid];
            for (int cc = 0; cc < 64; ++cc) s = fmaf(w_fc1[tid * 64 + cc], pooled[cc], s);
            hh[tid] = fmaxf(s, 0.f);
        }
        __syncthreads();
        if (tid < 64) {
            float sc = b_fc2[tid];
#pragma unroll
            for (int j = 0; j < 4; ++j) sc = fmaf(w_fc2[tid * 4 + j], hh[j], sc);
            fm[tid] = inv / (1.f + expf(-sc));
        }
        __syncthreads();
    }

    const float* srcb = src + (size_t)b * cin * HW + pix0;

    auto issue_x = [&](int cs, int buf) {
        const float* base = srcb + (size_t)(cs * 32) * HW;
        unsigned db = smb + (buf ? XS1_OFF : XS0_OFF);
#pragma unroll
        for (int k = 0; k < 8; ++k) {
            int seg = tid + k * 128;               // 0..1023
            int row = seg >> 5, off = (seg & 31) * 4;
            cpa16(db + (unsigned)(row * XSP + off) * 4, base + (size_t)row * HW + off);
        }
    };

    issue_x(0, 0); CPCOMMIT();
    if (CH > 1) { issue_x(1, 1); CPCOMMIT(); }

    float acc[2][8][4];
#pragma unroll
    for (int mt = 0; mt < 2; ++mt)
#pragma unroll
        for (int nt = 0; nt < 8; ++nt)
#pragma unroll
            for (int i = 0; i < 4; ++i) acc[mt][nt][i] = 0.f;

    int arow  = (lane & 7) + ((lane >> 4) << 3);
    int acol0 = (w << 5) + (((lane >> 3) & 1) << 3);
    int brow2 = ((lane >> 4) << 3) + (lane & 7);
    int bcol  = ((lane >> 3) & 1) << 3;

    for (int s = 0; s < CH; ++s) {
        if (s + 1 < CH) cpwait<1>(); else cpwait<0>();
        __syncthreads();

        // ---- W LDG first (L2-hot; latency hidden behind X convert below)
        int wo = tid >> 1, wc = (tid & 1) * 16;
        const float* wp = wsrc + wo * wrow + s * 32 + wc;
        float4 wa = *(const float4*)wp;
        float4 wb4 = *(const float4*)(wp + 4);
        float4 wcv = *(const float4*)(wp + 8);
        float4 wd = *(const float4*)(wp + 12);

        // ---- X convert: XS[s&1] fp32 [c][pix] -> XH/XL bf16
        {
            const char* xs = sm + ((s & 1) ? XS1_OFF : XS0_OFF);
            int cw = w * 32;
            unsigned hibuf[16], lobuf[16];
#pragma unroll
            for (int i = 0; i < 8; ++i) {
                float4 v = *(const float4*)(xs + (lane * XSP + cw + i * 4) * 4);
                float h0 = __bfloat162float(__float2bfloat16(v.x));
                float h1 = __bfloat162float(__float2bfloat16(v.y));
                float h2 = __bfloat162float(__float2bfloat16(v.z));
                float h3 = __bfloat162float(__float2bfloat16(v.w));
                hibuf[i * 2]     = pk(h0, h1);
                hibuf[i * 2 + 1] = pk(h2, h3);
                lobuf[i * 2]     = pk(v.x - h0, v.y - h1);
                lobuf[i * 2 + 1] = pk(v.z - h2, v.w - h3);
            }
            unsigned xoff = (unsigned)((lane * XPITCH + cw) * 2);
#pragma unroll
            for (int j = 0; j < 4; ++j) {
                *(uint4*)(sm + XH_OFF + xoff + j * 16) =
                    make_uint4(hibuf[j * 4], hibuf[j * 4 + 1], hibuf[j * 4 + 2], hibuf[j * 4 + 3]);
                *(uint4*)(sm + XL_OFF + xoff + j * 16) =
                    make_uint4(lobuf[j * 4], lobuf[j * 4 + 1], lobuf[j * 4 + 2], lobuf[j * 4 + 3]);
            }
        }

        // ---- W split + STS (FOLD: scale by fm first)
        {
            float wv[16] = {wa.x, wa.y, wa.z, wa.w, wb4.x, wb4.y, wb4.z, wb4.w,
                            wcv.x, wcv.y, wcv.z, wcv.w, wd.x, wd.y, wd.z, wd.w};
            if (FOLD) {
                const float* fm = (const float*)(sm + FM_OFF);
#pragma unroll
                for (int i = 0; i < 16; ++i) wv[i] *= fm[s * 32 + wc + i];
            }
#pragma unroll
            for (int i = 0; i < 4; ++i) {
                float h0 = __bfloat162float(__float2bfloat16(wv[i * 4]));
                float h1 = __bfloat162float(__float2bfloat16(wv[i * 4 + 1]));
                float h2 = __bfloat162float(__float2bfloat16(wv[i * 4 + 2]));
                float h3 = __bfloat162float(__float2bfloat16(wv[i * 4 + 3]));
                unsigned p0 = pk(h0, h1), p1 = pk(h2, h3);
                unsigned q0 = pk(wv[i * 4] - h0, wv[i * 4 + 1] - h1);
                unsigned q1 = pk(wv[i * 4 + 2] - h2, wv[i * 4 + 3] - h3);
                unsigned woff = (unsigned)((wo * WPITCH + wc + i * 4) * 2);
                *(uint2*)(sm + WH_OFF + woff) = make_uint2(p0, p1);
                *(uint2*)(sm + WL_OFF + woff) = make_uint2(q0, q1);
            }
        }
        __syncthreads();

        if (s + 2 < CH) { issue_x(s + 2, s & 1); CPCOMMIT(); }

        // ---- MMA: 2 k-steps of 16
#pragma unroll
        for (int ks = 0; ks < 2; ++ks) {
            unsigned ah[2][4], al[2][4];
#pragma unroll
            for (int mt = 0; mt < 2; ++mt) {
                unsigned aoff = (unsigned)(((ks * 16 + arow) * XPITCH + acol0 + mt * 16) * 2);
                ldsm4t(ah[mt][0], ah[mt][1], ah[mt][2], ah[mt][3], smb + XH_OFF + aoff);
                ldsm4t(al[mt][0], al[mt][1], al[mt][2], al[mt][3], smb + XL_OFF + aoff);
            }
#pragma unroll
            for (int ntp = 0; ntp < 4; ++ntp) {
                unsigned bh[4], bl[4];
                unsigned boff = (unsigned)(((ntp * 16 + brow2) * WPITCH + ks * 16 + bcol) * 2);
                ldsm4(bh[0], bh[1], bh[2], bh[3], smb + WH_OFF + boff);
                ldsm4(bl[0], bl[1], bl[2], bl[3], smb + WL_OFF + boff);
#pragma unroll
                for (int mt = 0; mt < 2; ++mt) {
                    mma16816(acc[mt][ntp * 2],     ah[mt], bh[0], bh[1]);
                    mma16816(acc[mt][ntp * 2],     al[mt], bh[0], bh[1]);
                    mma16816(acc[mt][ntp * 2],     ah[mt], bl[0], bl[1]);
                    mma16816(acc[mt][ntp * 2 + 1], ah[mt], bh[2], bh[3]);
                    mma16816(acc[mt][ntp * 2 + 1], al[mt], bh[2], bh[3]);
                    mma16816(acc[mt][ntp * 2 + 1], ah[mt], bl[2], bl[3]);
                }
            }
        }
    }

    // ---- epilogue
    int g  = lane >> 2;
    int t2 = (lane & 3) * 2;
#pragma unroll
    for (int mt = 0; mt < 2; ++mt) {
        float* dp = dst + (size_t)b * CMID * HW + pix0 + w * 32 + mt * 16;
#pragma unroll
        for (int nt = 0; nt < 8; ++nt) {
            int o0 = nt * 8 + t2;
            float b0 = __ldg(bias + o0), b1 = __ldg(bias + o0 + 1);
            dp[(size_t)o0 * HW + g]           = acc[mt][nt][0] + b0;
            dp[(size_t)(o0 + 1) * HW + g]     = acc[mt][nt][1] + b1;
            dp[(size_t)o0 * HW + g + 8]       = acc[mt][nt][2] + b0;
            dp[(size_t)(o0 + 1) * HW + g + 8] = acc[mt][nt][3] + b1;
        }
    }
}

// ---------------------------------------------------------------------------
// Fused depthwise stage, register-rolling rewrite (2.3x fewer LDS bytes).
// invS dropped: edge is linear in sm, and both g_sums and g_maxbits scale
// identically, so the max-normalized pipeline is scale-invariant.
__global__ void __launch_bounds__(256) k_edge() {
    __shared__ float ys[38][40];  // y, rows ty0-3.., cols tx0-3..
    __shared__ float ts[34][40];  // vertical gauss, rows ty0-1..
    __shared__ float ss[34][36];  // smoothed, rows ty0-1.., cols tx0-1..
    __shared__ float rs[8], rm[8];

    int tid   = threadIdx.x;
    int plane = blockIdx.y;
    int tile  = blockIdx.x;
    int ty0 = (tile >> 3) * 32;
    int tx0 = (tile & 7) * 32;
    const float* yp = g_y + (size_t)plane * HW;

    // ---- pass 1: load y tile + halo (zero pad)
    for (int i = tid; i < 38 * 38; i += 256) {
        int r = i / 38, c = i - r * 38;
        int gy = ty0 - 3 + r, gx = tx0 - 3 + c;
        float v = 0.f;
        if ((unsigned)gy < 256u && (unsigned)gx < 256u) v = yp[gy * 256 + gx];
        ys[r][c] = v;
    }
    __syncthreads();

    const float g1 = expf(-0.125f), g2 = expf(-0.5f);

    // ---- pass 2: vertical gaussian, rolling window (col, 6-row group)
    if (tid < 228) {
        int c = tid % 38, rg = tid / 38;    // 38 cols x 6 rowgroups
        int k0 = rg * 6;
        float y0 = ys[k0][c],     y1 = ys[k0 + 1][c], y2 = ys[k0 + 2][c];
        float y3 = ys[k0 + 3][c], y4 = ys[k0 + 4][c];
#pragma unroll
        for (int j = 0; j < 6; ++j) {
            int k = k0 + j;
            if (k < 34) {
                ts[k][c] = g2 * (y0 + y4) + g1 * (y1 + y3) + y2;
                y0 = y1; y1 = y2; y2 = y3; y3 = y4;
                if (k + 5 < 38) y4 = ys[k + 5][c];
            }
        }
    }
    __syncthreads();

    // ---- pass 3: horizontal gaussian, rolling window (row, 5-col group)
    if (tid < 238) {
        int r = tid / 7, cg = tid % 7;      // 34 rows x 7 colgroups
        int j0 = cg * 5;
        float t0 = ts[r][j0],     t1 = ts[r][j0 + 1], t2 = ts[r][j0 + 2];
        float t3 = ts[r][j0 + 3], t4 = ts[r][j0 + 4];
        int gy = ty0 - 1 + r;
#pragma unroll
        for (int u = 0; u < 5; ++u) {
            int j = j0 + u;
            if (j < 34) {
                float v = g2 * (t0 + t4) + g1 * (t1 + t3) + t2;
                int gx = tx0 - 1 + j;
                if ((unsigned)gy >= 256u || (unsigned)gx >= 256u) v = 0.f;
                ss[r][j] = v;
                t0 = t1; t1 = t2; t2 = t3; t3 = t4;
                if (j + 5 < 38) t4 = ts[r][j + 5];
            }
        }
    }
    __syncthreads();

    // ---- final: 2x2 output block per thread (16 LDS for 4 pixels)
    int tx = tid & 15, ty = tid >> 4;
    int r0 = 2 * ty, c0 = 2 * tx;
    float sv[4][4];
#pragma unroll
    for (int a2 = 0; a2 < 4; ++a2)
#pragma unroll
        for (int b2 = 0; b2 < 4; ++b2) sv[a2][b2] = ss[r0 + a2][c0 + b2];

    float lsum = 0.f, lmax = 0.f;
    float* ep = g_edge + (size_t)plane * HW;
#pragma unroll
    for (int dr = 0; dr < 2; ++dr)
#pragma unroll
        for (int dc = 0; dc < 2; ++dc) {
            float a  = sv[dr][dc],     bb = sv[dr][dc + 1],     cv = sv[dr][dc + 2];
            float d  = sv[dr + 1][dc], e  = sv[dr + 1][dc + 1], f  = sv[dr + 1][dc + 2];
            float g  = sv[dr + 2][dc], h  = sv[dr + 2][dc + 1], ii = sv[dr + 2][dc + 2];
            float g0  = 3.f * (a - cv) + 10.f * (d - f) + 3.f * (g - ii);
            float g90 = 3.f * (a - g)  + 10.f * (bb - h) + 3.f * (cv - ii);
            float lap = 4.f * e - bb - d - f - h;
            float edge = fmaxf(fabsf(g0), fabsf(g90)) + 0.1f * fabsf(lap);
            ep[(ty0 + r0 + dr) * 256 + tx0 + c0 + dc] = edge;
            lsum += edge;
            lmax = fmaxf(lmax, edge);
        }

    // ---- block reduction -> atomics
#pragma unroll
    for (int off = 16; off; off >>= 1) {
        lsum += __shfl_down_sync(0xffffffffu, lsum, off);
        lmax = fmaxf(lmax, __shfl_down_sync(0xffffffffu, lmax, off));
    }
    int wid = tid >> 5, lane = tid & 31;
    if (lane == 0) { rs[wid] = lsum; rm[wid] = lmax; }
    __syncthreads();
    if (tid == 0) {
        float s = 0.f, m = 0.f;
#pragma unroll
        for (int w2 = 0; w2 < 8; ++w2) { s += rs[w2]; m = fmaxf(m, rm[w2]); }
        atomicAdd(&g_sums[plane], s);
        atomicMax(&g_maxbits, __float_as_uint(m));
    }
}

// ---------------------------------------------------------------------------
extern "C" void kernel_launch(void* const* d_in, const int* in_sizes, int n_in,
                              void* d_out, int out_size) {
    const float* x     = (const float*)d_in[0];
    const float* w_in  = (const float*)d_in[1];
    const float* b_in  = (const float*)d_in[2];
    const float* w_fc1 = (const float*)d_in[3];
    const float* b_fc1 = (const float*)d_in[4];
    const float* w_fc2 = (const float*)d_in[5];
    const float* b_fc2 = (const float*)d_in[6];
    const float* w_out = (const float*)d_in[7];
    const float* b_out = (const float*)d_in[8];
    float* out = (float*)d_out;

    cudaFuncSetAttribute(k_conv<8, 0>, cudaFuncAttributeMaxDynamicSharedMemorySize, SMEM_SZ);
    cudaFuncSetAttribute(k_conv<2, 1>, cudaFuncAttributeMaxDynamicSharedMemorySize, SMEM_SZ);

    float* gy = nullptr;
    float* gedge = nullptr;
    cudaGetSymbolAddress((void**)&gy, g_y);
    cudaGetSymbolAddress((void**)&gedge, g_edge);

    k_conv<8, 0><<<2048, 128, SMEM_SZ>>>(x, 256, w_in, 256, b_in, gy,
                                         nullptr, nullptr, nullptr, nullptr);
    k_edge<<<dim3(64, 256), 256>>>();
    k_conv<2, 1><<<2048, 128, SMEM_SZ>>>(gedge, 64, w_out, 64, b_out, out,
                                         w_fc1, b_fc1, w_fc2, b_fc2);
}